// round 10
// baseline (speedup 1.0000x reference)
#include <cuda_runtime.h>
#include <cuda_bf16.h>
#include <cstdint>

// Problem constants
#define B_  2
#define S_  2048
#define D_  2560
#define H_  32
#define HD_ 80
#define RD_ 32

constexpr int M_ROWS = B_ * S_;       // 4096
constexpr int QKV_N  = 3 * D_;        // 7680

// Scratch (no allocation allowed -> __device__ globals)
__device__ float g_qkv[(size_t)M_ROWS * QKV_N];   // fp32 qkv from GEMM1
// bf16 hi/lo split operands for GEMMs
__device__ __align__(256) __nv_bfloat16 g_ahi[(size_t)M_ROWS * D_];   // x / ctx
__device__ __align__(256) __nv_bfloat16 g_alo[(size_t)M_ROWS * D_];
__device__ __align__(256) __nv_bfloat16 g_whi[(size_t)QKV_N  * D_];
__device__ __align__(256) __nv_bfloat16 g_wlo[(size_t)QKV_N  * D_];
__device__ __align__(256) __nv_bfloat16 g_ohi[(size_t)D_ * D_];
__device__ __align__(256) __nv_bfloat16 g_olo[(size_t)D_ * D_];
// head-major pre-split q/k/v: [b][h][s][80]
constexpr size_t HM_SZ = (size_t)B_ * H_ * S_ * HD_;
__device__ __align__(256) __nv_bfloat16 g_qh[HM_SZ], g_ql[HM_SZ];
__device__ __align__(256) __nv_bfloat16 g_kh[HM_SZ], g_kl[HM_SZ];
__device__ __align__(256) __nv_bfloat16 g_vh[HM_SZ], g_vl[HM_SZ];

// ---------------------------------------------------------------------------
// PTX helpers
// ---------------------------------------------------------------------------
__device__ __forceinline__ uint32_t smem_u32(const void* p) {
    uint32_t a;
    asm("{ .reg .u64 t; cvta.to.shared.u64 t, %1; cvt.u32.u64 %0, t; }"
        : "=r"(a) : "l"(p));
    return a;
}
__device__ __forceinline__ void ldsm4u(uint32_t* r, uint32_t addr) {
    asm volatile("ldmatrix.sync.aligned.m8n8.x4.shared.b16 {%0,%1,%2,%3}, [%4];"
                 : "=r"(r[0]), "=r"(r[1]), "=r"(r[2]), "=r"(r[3]) : "r"(addr));
}
__device__ __forceinline__ void ldsm4t(uint32_t* r, uint32_t addr) {
    asm volatile("ldmatrix.sync.aligned.m8n8.x4.trans.shared.b16 {%0,%1,%2,%3}, [%4];"
                 : "=r"(r[0]), "=r"(r[1]), "=r"(r[2]), "=r"(r[3]) : "r"(addr));
}
__device__ __forceinline__ void mma16816(float* c, const uint32_t* a,
                                         uint32_t b0, uint32_t b1)
{
    asm volatile(
        "mma.sync.aligned.m16n8k16.row.col.f32.bf16.bf16.f32 "
        "{%0,%1,%2,%3}, {%4,%5,%6,%7}, {%8,%9}, {%0,%1,%2,%3};"
        : "+f"(c[0]), "+f"(c[1]), "+f"(c[2]), "+f"(c[3])
        : "r"(a[0]), "r"(a[1]), "r"(a[2]), "r"(a[3]), "r"(b0), "r"(b1));
}
__device__ __forceinline__ void cp_async16(uint32_t dst, const void* src) {
    asm volatile("cp.async.cg.shared.global [%0], [%1], 16;"
                 :: "r"(dst), "l"((unsigned long long)__cvta_generic_to_global(src)));
}
#define CP_COMMIT() asm volatile("cp.async.commit_group;" ::: "memory")

#define SWZ64(o) ((o) ^ (((o) >> 3) & 0x30))

__device__ __forceinline__ void split2(float x, float y, uint32_t& hi, uint32_t& lo) {
    __nv_bfloat162 h = __floats2bfloat162_rn(x, y);
    float2 f = __bfloat1622float2(h);
    __nv_bfloat162 l = __floats2bfloat162_rn(x - f.x, y - f.y);
    hi = *(uint32_t*)&h;
    lo = *(uint32_t*)&l;
}
__device__ __forceinline__ void split4(float4 v, uint2& hi, uint2& lo) {
    split2(v.x, v.y, hi.x, lo.x);
    split2(v.z, v.w, hi.y, lo.y);
}

// ---------------------------------------------------------------------------
// fp32 -> bf16 hi/lo split (elementwise, same layout)
// ---------------------------------------------------------------------------
__global__ void cvt_split(const float4* __restrict__ in, uint2* __restrict__ hi,
                          uint2* __restrict__ lo, int n4)
{
    int i = blockIdx.x * blockDim.x + threadIdx.x;
    if (i >= n4) return;
    uint2 h, l;
    split4(in[i], h, l);
    hi[i] = h;
    lo[i] = l;
}

// ---------------------------------------------------------------------------
// RoPE (in-place on fp32 qkv) -- separate pass (proven)
// ---------------------------------------------------------------------------
__global__ void rope_kernel(float* __restrict__ qkv)
{
    int idx = blockIdx.x * blockDim.x + threadIdx.x;
    const int total = B_ * S_ * 2 * H_ * (RD_ / 2);
    if (idx >= total) return;
    const int i    = idx & 15;  idx >>= 4;
    const int h    = idx & 31;  idx >>= 5;
    const int part = idx & 1;   idx >>= 1;
    const int s    = idx & (S_ - 1); idx >>= 11;
    const int b    = idx;

    const double inv = exp2(-(double)i * (13.287712379549449 / 16.0));
    const float ang  = (float)((double)s * inv);
    const float c  = cosf(ang);
    const float si = sinf(ang);

    const size_t base = ((size_t)(b * S_ + s)) * QKV_N + (size_t)part * D_ + h * HD_;
    const float t1 = qkv[base + i];
    const float t2 = qkv[base + 16 + i];
    qkv[base + i]      = t1 * c  - t2 * si;
    qkv[base + 16 + i] = t1 * si + t2 * c;
}

// ---------------------------------------------------------------------------
// qkv fp32 (post-rope) -> head-major bf16 hi/lo; 1/sqrt(80) folded into q.
// ---------------------------------------------------------------------------
__global__ void cvt_qkv(const float4* __restrict__ qkv4)
{
    int idx = blockIdx.x * blockDim.x + threadIdx.x;
    const int n4 = M_ROWS * QKV_N / 4;
    if (idx >= n4) return;
    const int col4 = idx % (QKV_N / 4);
    const int rowm = idx / (QKV_N / 4);      // b*S + s
    const int col  = col4 * 4;
    const int part = col / D_;
    const int win  = col % D_;
    const int h    = win / HD_;
    const int d    = win % HD_;
    const int b    = rowm >> 11;
    const int s    = rowm & (S_ - 1);

    float4 v = qkv4[idx];
    if (part == 0) {   // fold softmax scale into q
        const float scale = 0.11180339887498949f;
        v.x *= scale; v.y *= scale; v.z *= scale; v.w *= scale;
    }

    uint2 hi, lo;
    split4(v, hi, lo);
    const size_t dst = (((size_t)(b * H_ + h)) * S_ + s) * HD_ + d;
    __nv_bfloat16 *ph, *pl;
    if (part == 0)      { ph = g_qh; pl = g_ql; }
    else if (part == 1) { ph = g_kh; pl = g_kl; }
    else                { ph = g_vh; pl = g_vl; }
    *(uint2*)&ph[dst] = hi;
    *(uint2*)&pl[dst] = lo;
}

// ---------------------------------------------------------------------------
// HMMA bf16x3 NT GEMM (128x128 CTA, warp 32x64, BK=32, 3-stage cp.async,
// single __syncthreads per stage -- verified, unchanged).
// ---------------------------------------------------------------------------
constexpr int GEMM_SMEM = 3 * 32768;

__global__ __launch_bounds__(256, 2)
void gemm_hmma(const __nv_bfloat16* __restrict__ Ahi, const __nv_bfloat16* __restrict__ Alo,
               const __nv_bfloat16* __restrict__ Bhi, const __nv_bfloat16* __restrict__ Blo,
               const float* __restrict__ bias, float* __restrict__ C,
               int M, int N, int K)
{
    extern __shared__ __align__(1024) char gsm[];
    const uint32_t sb = smem_u32(gsm);
    const int tid  = threadIdx.x;
    const int lane = tid & 31;
    const int wid  = tid >> 5;
    const int wm0  = (wid & 3) * 32;
    const int wn0  = (wid >> 2) * 64;
    const int bm   = blockIdx.y * 128;
    const int bn   = blockIdx.x * 128;
    const int lr   = lane & 7;
    const int g    = lane >> 3;

    const __nv_bfloat16* s0 = Ahi + (size_t)bm * K;
    const __nv_bfloat16* s1 = Alo + (size_t)bm * K;
    const __nv_bfloat16* s2 = Bhi + (size_t)bn * K;
    const __nv_bfloat16* s3 = Blo + (size_t)bn * K;

    float acc[2][8][4] = {};

    auto load_stage = [&](int s) {
        const uint32_t st = sb + (uint32_t)(s % 3) * 32768;
        #pragma unroll
        for (int it = 0; it < 8; ++it) {
            const int tile = it >> 1;
            const int idx  = tid + (it & 1) * 256;
            const int row  = idx >> 2;
            const int c    = idx & 3;
            const __nv_bfloat16* base =
                (tile == 0) ? s0 : (tile == 1) ? s1 : (tile == 2) ? s2 : s3;
            const __nv_bfloat16* gp = base + (size_t)row * K + s * 32 + c * 8;
            cp_async16(st + tile * 8192 + SWZ64((uint32_t)(row * 64 + c * 16)), gp);
        }
        CP_COMMIT();
    };

    const int nst = K >> 5;
    load_stage(0);
    load_stage(1);

    for (int s = 0; s < nst; ++s) {
        if (s + 1 < nst)
            asm volatile("cp.async.wait_group 1;" ::: "memory");
        else
            asm volatile("cp.async.wait_group 0;" ::: "memory");
        __syncthreads();
        if (s + 2 < nst) load_stage(s + 2);   // writes buf (s-1)%3: readers passed sync

        const uint32_t st = sb + (uint32_t)(s % 3) * 32768;
        #pragma unroll
        for (int ks = 0; ks < 2; ++ks) {
            uint32_t ah[2][4], al[2][4];
            #pragma unroll
            for (int mi = 0; mi < 2; ++mi) {
                const uint32_t ro = (uint32_t)((wm0 + mi * 16 + lr + (g & 1) * 8) * 64
                                               + ks * 32 + (g >> 1) * 16);
                ldsm4u(ah[mi], st + SWZ64(ro));
                ldsm4u(al[mi], st + 8192 + SWZ64(ro));
            }
            #pragma unroll
            for (int np = 0; np < 4; ++np) {
                const uint32_t ro = (uint32_t)((wn0 + np * 16 + lr + (g >> 1) * 8) * 64
                                               + ks * 32 + (g & 1) * 16);
                uint32_t bh[4], bl[4];
                ldsm4u(bh, st + 16384 + SWZ64(ro));
                ldsm4u(bl, st + 24576 + SWZ64(ro));
                #pragma unroll
                for (int half = 0; half < 2; ++half) {
                    const int ni = np * 2 + half;
                    #pragma unroll
                    for (int mi = 0; mi < 2; ++mi) {
                        mma16816(acc[mi][ni], ah[mi], bh[half * 2], bh[half * 2 + 1]);
                        mma16816(acc[mi][ni], ah[mi], bl[half * 2], bl[half * 2 + 1]);
                        mma16816(acc[mi][ni], al[mi], bh[half * 2], bh[half * 2 + 1]);
                    }
                }
            }
        }
    }

    #pragma unroll
    for (int ni = 0; ni < 8; ++ni) {
        const int col = bn + wn0 + ni * 8 + (lane & 3) * 2;
        const float2 bv = *(const float2*)&bias[col];
        #pragma unroll
        for (int mi = 0; mi < 2; ++mi) {
            const int row = bm + wm0 + mi * 16 + (lane >> 2);
            *(float2*)&C[(size_t)row * N + col] =
                make_float2(acc[mi][ni][0] + bv.x, acc[mi][ni][1] + bv.y);
            *(float2*)&C[(size_t)(row + 8) * N + col] =
                make_float2(acc[mi][ni][2] + bv.x, acc[mi][ni][3] + bv.y);
        }
    }
}

// ---------------------------------------------------------------------------
// Causal flash attention, HMMA bf16x3, x4-ldmatrix loads (round-9 verified).
// SINGLE CHANGE this round: __launch_bounds__(256, 2) -> 2 CTAs/SM
// (smem 2x90112 = 180224 B fits; regs capped at 128).
// ---------------------------------------------------------------------------
constexpr int ATTN_SMEM = 2 * 45056;   // 90112

__global__ __launch_bounds__(256, 2)
void attn_tc(const __nv_bfloat16* __restrict__ qh_g, const __nv_bfloat16* __restrict__ ql_g,
             const __nv_bfloat16* __restrict__ kh_g, const __nv_bfloat16* __restrict__ kl_g,
             const __nv_bfloat16* __restrict__ vh_g, const __nv_bfloat16* __restrict__ vl_g,
             __nv_bfloat16* __restrict__ chi, __nv_bfloat16* __restrict__ clo)
{
    extern __shared__ __align__(1024) char smc[];
    const uint32_t sb = smem_u32(smc);
    const int qt   = gridDim.x - 1 - blockIdx.x;   // big tiles first
    const int h    = blockIdx.y;
    const int b    = blockIdx.z;
    const int tid  = threadIdx.x;
    const int lane = tid & 31;
    const int wid  = tid >> 5;
    const int wm   = wid * 16;
    const int lr   = lane & 7;
    const int g    = lane >> 3;

    const size_t hb = ((size_t)(b * H_ + h)) * S_ * HD_;

    // ---- stage Q (hi at 0, lo at 22528) and load fragments ----
    for (int t = tid; t < 2560; t += 256) {
        const int arr = t / 1280, rem = t % 1280;
        const int row = rem / 10, c = rem % 10;
        const __nv_bfloat16* src = (arr ? ql_g : qh_g) + hb
                                   + (size_t)(qt * 128 + row) * HD_ + c * 8;
        cp_async16(sb + (uint32_t)(arr * 22528 + row * 176 + c * 16), src);
    }
    CP_COMMIT();
    asm volatile("cp.async.wait_group 0;" ::: "memory");
    __syncthreads();

    uint32_t qh[5][4], ql[5][4];
    #pragma unroll
    for (int ks = 0; ks < 5; ++ks) {
        const uint32_t ro = (uint32_t)((wm + lr + (g & 1) * 8) * 176 + ks * 32 + (g >> 1) * 16);
        ldsm4u(qh[ks], sb + ro);
        ldsm4u(ql[ks], sb + 22528 + ro);
    }
    __syncthreads();

    auto load_kv = [&](int kt) {
        const uint32_t st = sb + (uint32_t)(kt & 1) * 45056;
        const __nv_bfloat16* srcs[4] = { kh_g, kl_g, vh_g, vl_g };
        #pragma unroll
        for (int it = 0; it < 10; ++it) {
            const int t = tid + it * 256;
            const int arr = t / 640, rem = t % 640;
            const int row = rem / 10, c = rem % 10;
            const __nv_bfloat16* src = srcs[arr] + hb
                                       + (size_t)(kt * 64 + row) * HD_ + c * 8;
            cp_async16(st + (uint32_t)(arr * 11264 + row * 176 + c * 16), src);
        }
        CP_COMMIT();
    };

    float o[10][4] = {};
    float mx0 = -1e30f, mx1 = -1e30f, l0 = 0.f, l1 = 0.f;
    const int nkt = 2 * qt + 2;

    load_kv(0);

    // x4 ldmatrix lane-address components (conflict-free)
    const uint32_t krow = (uint32_t)(((lane >> 4) * 8 + lr) * 176 + ((lane >> 3) & 1) * 16);
    const uint32_t vrow = (uint32_t)((((lane >> 3) & 1) * 8 + lr) * 176 + (lane >> 4) * 16);

    for (int kt = 0; kt < nkt; ++kt) {
        if (kt + 1 < nkt) {
            load_kv(kt + 1);
            asm volatile("cp.async.wait_group 1;" ::: "memory");
        } else {
            asm volatile("cp.async.wait_group 0;" ::: "memory");
        }
        __syncthreads();

        const bool active = (qt * 128 + wm + 15 >= kt * 64);
        if (active) {
            const uint32_t st = sb + (uint32_t)(kt & 1) * 45056;

            // ---- scores S = Q K^T (bf16x3), 16 keys per ldsm.x4 ----
            float s[8][4];
            #pragma unroll
            for (int nb2 = 0; nb2 < 4; ++nb2) {
                float* sA = s[nb2 * 2];
                float* sB = s[nb2 * 2 + 1];
                sA[0] = sA[1] = sA[2] = sA[3] = 0.f;
                sB[0] = sB[1] = sB[2] = sB[3] = 0.f;
                const uint32_t rbase = st + (uint32_t)(nb2 * 16 * 176) + krow;
                #pragma unroll
                for (int ks = 0; ks < 5; ++ks) {
                    uint32_t kh4[4], kl4[4];
                    const uint32_t ro = rbase + ks * 32;
                    ldsm4u(kh4, ro);
                    ldsm4u(kl4, ro + 11264);
                    mma16816(sA, qh[ks], kh4[0], kh4[1]);
                    mma16816(sA, qh[ks], kl4[0], kl4[1]);
                    mma16816(sA, ql[ks], kh4[0], kh4[1]);
                    mma16816(sB, qh[ks], kh4[2], kh4[3]);
                    mma16816(sB, qh[ks], kl4[2], kl4[3]);
                    mma16816(sB, ql[ks], kh4[2], kh4[3]);
                }
            }
            if (kt >= 2 * qt) {   // diagonal-region mask
                const int r0 = qt * 128 + wm + (lane >> 2);
                #pragma unroll
                for (int nb = 0; nb < 8; ++nb) {
                    const int c0 = kt * 64 + nb * 8 + (lane & 3) * 2;
                    if (c0     > r0)     s[nb][0] = -1e30f;
                    if (c0 + 1 > r0)     s[nb][1] = -1e30f;
                    if (c0     > r0 + 8) s[nb][2] = -1e30f;
                    if (c0 + 1 > r0 + 8) s[nb][3] = -1e30f;
                }
            }

            // ---- online softmax ----
            float m0 = -1e30f, m1 = -1e30f;
            #pragma unroll
            for (int nb = 0; nb < 8; ++nb) {
                m0 = fmaxf(m0, fmaxf(s[nb][0], s[nb][1]));
                m1 = fmaxf(m1, fmaxf(s[nb][2], s[nb][3]));
            }
            m0 = fmaxf(m0, __shfl_xor_sync(0xffffffffu, m0, 1));
            m0 = fmaxf(m0, __shfl_xor_sync(0xffffffffu, m0, 2));
            m1 = fmaxf(m1, __shfl_xor_sync(0xffffffffu, m1, 1));
            m1 = fmaxf(m1, __shfl_xor_sync(0xffffffffu, m1, 2));
            const float mn0 = fmaxf(mx0, m0), mn1 = fmaxf(mx1, m1);
            const float corr0 = __expf(mx0 - mn0), corr1 = __expf(mx1 - mn1);
            mx0 = mn0; mx1 = mn1;
            float sum0 = 0.f, sum1 = 0.f;
            #pragma unroll
            for (int nb = 0; nb < 8; ++nb) {
                s[nb][0] = __expf(s[nb][0] - mn0);
                s[nb][1] = __expf(s[nb][1] - mn0);
                s[nb][2] = __expf(s[nb][2] - mn1);
                s[nb][3] = __expf(s[nb][3] - mn1);
                sum0 += s[nb][0] + s[nb][1];
                sum1 += s[nb][2] + s[nb][3];
            }
            sum0 += __shfl_xor_sync(0xffffffffu, sum0, 1);
            sum0 += __shfl_xor_sync(0xffffffffu, sum0, 2);
            sum1 += __shfl_xor_sync(0xffffffffu, sum1, 1);
            sum1 += __shfl_xor_sync(0xffffffffu, sum1, 2);
            l0 = l0 * corr0 + sum0;
            l1 = l1 * corr1 + sum1;
            #pragma unroll
            for (int nd = 0; nd < 10; ++nd) {
                o[nd][0] *= corr0; o[nd][1] *= corr0;
                o[nd][2] *= corr1; o[nd][3] *= corr1;
            }

            // ---- P -> bf16 hi/lo fragments ----
            uint32_t ph[4][4], pl[4][4];
            #pragma unroll
            for (int kb = 0; kb < 4; ++kb) {
                split2(s[2 * kb][0],     s[2 * kb][1],     ph[kb][0], pl[kb][0]);
                split2(s[2 * kb][2],     s[2 * kb][3],     ph[kb][1], pl[kb][1]);
                split2(s[2 * kb + 1][0], s[2 * kb + 1][1], ph[kb][2], pl[kb][2]);
                split2(s[2 * kb + 1][2], s[2 * kb + 1][3], ph[kb][3], pl[kb][3]);
            }

            // ---- O += P V (bf16x3), two nd blocks per ldsm.x4.trans ----
            #pragma unroll
            for (int nd2 = 0; nd2 < 5; ++nd2) {
                float* oA = o[nd2 * 2];
                float* oB = o[nd2 * 2 + 1];
                const uint32_t cbase = st + 22528 + (uint32_t)(nd2 * 32) + vrow;
                #pragma unroll
                for (int kb = 0; kb < 4; ++kb) {
                    uint32_t vh4[4], vl4[4];
                    const uint32_t ro = cbase + (uint32_t)(kb * 16 * 176);
                    ldsm4t(vh4, ro);
                    ldsm4t(vl4, ro + 11264);
                    mma16816(oA, ph[kb], vh4[0], vh4[1]);
                    mma16816(oA, ph[kb], vl4[0], vl4[1]);
                    mma16816(oA, pl[kb], vh4[0], vh4[1]);
                    mma16816(oB, ph[kb], vh4[2], vh4[3]);
                    mma16816(oB, ph[kb], vl4[2], vl4[3]);
                    mma16816(oB, pl[kb], vh4[2], vh4[3]);
                }
            }
        }
        __syncthreads();
    }

    const float inv0 = 1.f / l0, inv1 = 1.f / l1;
    const int r0 = qt * 128 + wm + (lane >> 2);
    #pragma unroll
    for (int nd = 0; nd < 10; ++nd) {
        const int col = h * HD_ + nd * 8 + (lane & 3) * 2;
        uint32_t hi, lo;
        split2(o[nd][0] * inv0, o[nd][1] * inv0, hi, lo);
        *(uint32_t*)&chi[((size_t)(b * S_ + r0)) * D_ + col] = hi;
        *(uint32_t*)&clo[((size_t)(b * S_ + r0)) * D_ + col] = lo;
        split2(o[nd][2] * inv1, o[nd][3] * inv1, hi, lo);
        *(uint32_t*)&chi[((size_t)(b * S_ + r0 + 8)) * D_ + col] = hi;
        *(uint32_t*)&clo[((size_t)(b * S_ + r0 + 8)) * D_ + col] = lo;
    }
}

// ---------------------------------------------------------------------------
// Launch
// ---------------------------------------------------------------------------
extern "C" void kernel_launch(void* const* d_in, const int* in_sizes, int n_in,
                              void* d_out, int out_size)
{
    const float* x      = (const float*)d_in[0];
    const float* wqkv_w = (const float*)d_in[1];
    const float* wqkv_b = (const float*)d_in[2];
    const float* out_w  = (const float*)d_in[3];
    const float* out_b  = (const float*)d_in[4];
    float* out = (float*)d_out;

    float* qkv;
    __nv_bfloat16 *ahi, *alo, *whi, *wlo, *ohi, *olo;
    __nv_bfloat16 *qh, *ql, *kh, *kl, *vh, *vl;
    cudaGetSymbolAddress((void**)&qkv, g_qkv);
    cudaGetSymbolAddress((void**)&ahi, g_ahi);
    cudaGetSymbolAddress((void**)&alo, g_alo);
    cudaGetSymbolAddress((void**)&whi, g_whi);
    cudaGetSymbolAddress((void**)&wlo, g_wlo);
    cudaGetSymbolAddress((void**)&ohi, g_ohi);
    cudaGetSymbolAddress((void**)&olo, g_olo);
    cudaGetSymbolAddress((void**)&qh, g_qh);
    cudaGetSymbolAddress((void**)&ql, g_ql);
    cudaGetSymbolAddress((void**)&kh, g_kh);
    cudaGetSymbolAddress((void**)&kl, g_kl);
    cudaGetSymbolAddress((void**)&vh, g_vh);
    cudaGetSymbolAddress((void**)&vl, g_vl);

    cudaFuncSetAttribute(gemm_hmma,
                         cudaFuncAttributeMaxDynamicSharedMemorySize, GEMM_SMEM);
    cudaFuncSetAttribute(attn_tc,
                         cudaFuncAttributeMaxDynamicSharedMemorySize, ATTN_SMEM);

    // 0) split x / weights into bf16 hi/lo
    {
        const int n4x = M_ROWS * D_ / 4;
        cvt_split<<<n4x / 256, 256>>>((const float4*)x, (uint2*)ahi, (uint2*)alo, n4x);
        const int n4w = QKV_N * D_ / 4;
        cvt_split<<<n4w / 256, 256>>>((const float4*)wqkv_w, (uint2*)whi, (uint2*)wlo, n4w);
        const int n4o = D_ * D_ / 4;
        cvt_split<<<n4o / 256, 256>>>((const float4*)out_w, (uint2*)ohi, (uint2*)olo, n4o);
    }

    // 1) QKV = X @ Wqkv^T + b
    dim3 g1(QKV_N / 128, M_ROWS / 128);
    gemm_hmma<<<g1, 256, GEMM_SMEM>>>(ahi, alo, whi, wlo, wqkv_b, qkv,
                                      M_ROWS, QKV_N, D_);

    // 2) RoPE on q,k (fp32, separate pass)
    const int rope_total = B_ * S_ * 2 * H_ * (RD_ / 2);
    rope_kernel<<<rope_total / 256, 256>>>(qkv);

    // 3) split qkv -> head-major bf16 hi/lo (scale folded into q)
    cvt_qkv<<<(M_ROWS * QKV_N / 4) / 256, 256>>>((const float4*)qkv);

    // 4) causal attention -> ctx (written directly as hi/lo into ahi/alo)
    dim3 ga(S_ / 128, H_, B_);
    attn_tc<<<ga, 256, ATTN_SMEM>>>(qh, ql, kh, kl, vh, vl, ahi, alo);

    // 5) out = ctx @ Wout^T + b
    dim3 g2(D_ / 128, M_ROWS / 128);
    gemm_hmma<<<g2, 256, GEMM_SMEM>>>(ahi, alo, ohi, olo, out_b, out,
                                      M_ROWS, D_, D_);
}

// round 11
// speedup vs baseline: 1.0996x; 1.0996x over previous
#include <cuda_runtime.h>
#include <cuda_bf16.h>
#include <cstdint>

// Problem constants
#define B_  2
#define S_  2048
#define D_  2560
#define H_  32
#define HD_ 80
#define RD_ 32

constexpr int M_ROWS = B_ * S_;       // 4096
constexpr int QKV_N  = 3 * D_;        // 7680

// Scratch (no allocation allowed -> __device__ globals)
__device__ float g_qkv[(size_t)M_ROWS * QKV_N];   // fp32 qkv from GEMM1
__device__ float g_rope_tab[S_ * 32];             // [s][0..15]=cos, [16..31]=sin
// bf16 hi/lo split operands for GEMMs
__device__ __align__(256) __nv_bfloat16 g_ahi[(size_t)M_ROWS * D_];   // x / ctx
__device__ __align__(256) __nv_bfloat16 g_alo[(size_t)M_ROWS * D_];
__device__ __align__(256) __nv_bfloat16 g_whi[(size_t)QKV_N  * D_];
__device__ __align__(256) __nv_bfloat16 g_wlo[(size_t)QKV_N  * D_];
__device__ __align__(256) __nv_bfloat16 g_ohi[(size_t)D_ * D_];
__device__ __align__(256) __nv_bfloat16 g_olo[(size_t)D_ * D_];
// head-major pre-split q/k/v: [b][h][s][80]
constexpr size_t HM_SZ = (size_t)B_ * H_ * S_ * HD_;
__device__ __align__(256) __nv_bfloat16 g_qh[HM_SZ], g_ql[HM_SZ];
__device__ __align__(256) __nv_bfloat16 g_kh[HM_SZ], g_kl[HM_SZ];
__device__ __align__(256) __nv_bfloat16 g_vh[HM_SZ], g_vl[HM_SZ];

// ---------------------------------------------------------------------------
// PTX helpers
// ---------------------------------------------------------------------------
__device__ __forceinline__ uint32_t smem_u32(const void* p) {
    uint32_t a;
    asm("{ .reg .u64 t; cvta.to.shared.u64 t, %1; cvt.u32.u64 %0, t; }"
        : "=r"(a) : "l"(p));
    return a;
}
__device__ __forceinline__ void ldsm4u(uint32_t* r, uint32_t addr) {
    asm volatile("ldmatrix.sync.aligned.m8n8.x4.shared.b16 {%0,%1,%2,%3}, [%4];"
                 : "=r"(r[0]), "=r"(r[1]), "=r"(r[2]), "=r"(r[3]) : "r"(addr));
}
__device__ __forceinline__ void ldsm4t(uint32_t* r, uint32_t addr) {
    asm volatile("ldmatrix.sync.aligned.m8n8.x4.trans.shared.b16 {%0,%1,%2,%3}, [%4];"
                 : "=r"(r[0]), "=r"(r[1]), "=r"(r[2]), "=r"(r[3]) : "r"(addr));
}
__device__ __forceinline__ void mma16816(float* c, const uint32_t* a,
                                         uint32_t b0, uint32_t b1)
{
    asm volatile(
        "mma.sync.aligned.m16n8k16.row.col.f32.bf16.bf16.f32 "
        "{%0,%1,%2,%3}, {%4,%5,%6,%7}, {%8,%9}, {%0,%1,%2,%3};"
        : "+f"(c[0]), "+f"(c[1]), "+f"(c[2]), "+f"(c[3])
        : "r"(a[0]), "r"(a[1]), "r"(a[2]), "r"(a[3]), "r"(b0), "r"(b1));
}
__device__ __forceinline__ void cp_async16(uint32_t dst, const void* src) {
    asm volatile("cp.async.cg.shared.global [%0], [%1], 16;"
                 :: "r"(dst), "l"((unsigned long long)__cvta_generic_to_global(src)));
}
#define CP_COMMIT() asm volatile("cp.async.commit_group;" ::: "memory")

#define SWZ64(o) ((o) ^ (((o) >> 3) & 0x30))

__device__ __forceinline__ void split2(float x, float y, uint32_t& hi, uint32_t& lo) {
    __nv_bfloat162 h = __floats2bfloat162_rn(x, y);
    float2 f = __bfloat1622float2(h);
    __nv_bfloat162 l = __floats2bfloat162_rn(x - f.x, y - f.y);
    hi = *(uint32_t*)&h;
    lo = *(uint32_t*)&l;
}
__device__ __forceinline__ void split4(float4 v, uint2& hi, uint2& lo) {
    split2(v.x, v.y, hi.x, lo.x);
    split2(v.z, v.w, hi.y, lo.y);
}

// ---------------------------------------------------------------------------
// fp32 -> bf16 hi/lo split (elementwise, same layout)
// ---------------------------------------------------------------------------
__global__ void cvt_split(const float4* __restrict__ in, uint2* __restrict__ hi,
                          uint2* __restrict__ lo, int n4)
{
    int i = blockIdx.x * blockDim.x + threadIdx.x;
    if (i >= n4) return;
    uint2 h, l;
    split4(in[i], h, l);
    hi[i] = h;
    lo[i] = l;
}

// ---------------------------------------------------------------------------
// RoPE cos/sin table: same fp64 angle path as the proven rope_kernel.
// 32768 threads, runs in ~2us.
// ---------------------------------------------------------------------------
__global__ void rope_table_kernel()
{
    const int t = blockIdx.x * blockDim.x + threadIdx.x;   // 0..32767
    const int i = t & 15;
    const int s = t >> 4;
    const double inv = exp2(-(double)i * (13.287712379549449 / 16.0));
    const float ang  = (float)((double)s * inv);
    g_rope_tab[s * 32 + i]      = cosf(ang);
    g_rope_tab[s * 32 + 16 + i] = sinf(ang);
}

// ---------------------------------------------------------------------------
// Fused RoPE(table) + split: qkv fp32 -> head-major bf16 hi/lo q/k/v.
// 1/sqrt(80) folded into q. Same arithmetic as rope_kernel + old cvt_qkv.
// ---------------------------------------------------------------------------
__global__ void cvt_qkv(const float4* __restrict__ qkv4)
{
    int idx = blockIdx.x * blockDim.x + threadIdx.x;
    const int n4 = M_ROWS * QKV_N / 4;
    if (idx >= n4) return;
    const int col4 = idx % (QKV_N / 4);
    const int rowm = idx / (QKV_N / 4);      // b*S + s
    const int col  = col4 * 4;
    const int part = col / D_;
    const int win  = col % D_;
    const int h    = win / HD_;
    const int d    = win % HD_;
    const int b    = rowm >> 11;
    const int s    = rowm & (S_ - 1);

    float4 v = qkv4[idx];

    if (part < 2 && d < RD_) {
        const bool first = (d < 16);
        const int  i     = first ? d : d - 16;
        const float4 cv  = *(const float4*)&g_rope_tab[s * 32 + i];
        const float4 sv  = *(const float4*)&g_rope_tab[s * 32 + 16 + i];
        const float4 ov  = qkv4[idx + (first ? 4 : -4)];
        if (first) {   // r = t1*c - t2*si  (t1 = this, t2 = partner)
            v.x = v.x * cv.x - ov.x * sv.x;
            v.y = v.y * cv.y - ov.y * sv.y;
            v.z = v.z * cv.z - ov.z * sv.z;
            v.w = v.w * cv.w - ov.w * sv.w;
        } else {       // r = t1*si + t2*c  (t1 = partner, t2 = this)
            v.x = ov.x * sv.x + v.x * cv.x;
            v.y = ov.y * sv.y + v.y * cv.y;
            v.z = ov.z * sv.z + v.z * cv.z;
            v.w = ov.w * sv.w + v.w * cv.w;
        }
    }
    if (part == 0) {   // fold softmax scale into q
        const float scale = 0.11180339887498949f;
        v.x *= scale; v.y *= scale; v.z *= scale; v.w *= scale;
    }

    uint2 hi, lo;
    split4(v, hi, lo);
    const size_t dst = (((size_t)(b * H_ + h)) * S_ + s) * HD_ + d;
    __nv_bfloat16 *ph, *pl;
    if (part == 0)      { ph = g_qh; pl = g_ql; }
    else if (part == 1) { ph = g_kh; pl = g_kl; }
    else                { ph = g_vh; pl = g_vl; }
    *(uint2*)&ph[dst] = hi;
    *(uint2*)&pl[dst] = lo;
}

// ---------------------------------------------------------------------------
// HMMA bf16x3 NT GEMM (128x128 CTA, warp 32x64, BK=32, 3-stage cp.async,
// single __syncthreads per stage -- verified, unchanged).
// ---------------------------------------------------------------------------
constexpr int GEMM_SMEM = 3 * 32768;

__global__ __launch_bounds__(256, 2)
void gemm_hmma(const __nv_bfloat16* __restrict__ Ahi, const __nv_bfloat16* __restrict__ Alo,
               const __nv_bfloat16* __restrict__ Bhi, const __nv_bfloat16* __restrict__ Blo,
               const float* __restrict__ bias, float* __restrict__ C,
               int M, int N, int K)
{
    extern __shared__ __align__(1024) char gsm[];
    const uint32_t sb = smem_u32(gsm);
    const int tid  = threadIdx.x;
    const int lane = tid & 31;
    const int wid  = tid >> 5;
    const int wm0  = (wid & 3) * 32;
    const int wn0  = (wid >> 2) * 64;
    const int bm   = blockIdx.y * 128;
    const int bn   = blockIdx.x * 128;
    const int lr   = lane & 7;
    const int g    = lane >> 3;

    const __nv_bfloat16* s0 = Ahi + (size_t)bm * K;
    const __nv_bfloat16* s1 = Alo + (size_t)bm * K;
    const __nv_bfloat16* s2 = Bhi + (size_t)bn * K;
    const __nv_bfloat16* s3 = Blo + (size_t)bn * K;

    float acc[2][8][4] = {};

    auto load_stage = [&](int s) {
        const uint32_t st = sb + (uint32_t)(s % 3) * 32768;
        #pragma unroll
        for (int it = 0; it < 8; ++it) {
            const int tile = it >> 1;
            const int idx  = tid + (it & 1) * 256;
            const int row  = idx >> 2;
            const int c    = idx & 3;
            const __nv_bfloat16* base =
                (tile == 0) ? s0 : (tile == 1) ? s1 : (tile == 2) ? s2 : s3;
            const __nv_bfloat16* gp = base + (size_t)row * K + s * 32 + c * 8;
            cp_async16(st + tile * 8192 + SWZ64((uint32_t)(row * 64 + c * 16)), gp);
        }
        CP_COMMIT();
    };

    const int nst = K >> 5;
    load_stage(0);
    load_stage(1);

    for (int s = 0; s < nst; ++s) {
        if (s + 1 < nst)
            asm volatile("cp.async.wait_group 1;" ::: "memory");
        else
            asm volatile("cp.async.wait_group 0;" ::: "memory");
        __syncthreads();
        if (s + 2 < nst) load_stage(s + 2);   // writes buf (s-1)%3: readers passed sync

        const uint32_t st = sb + (uint32_t)(s % 3) * 32768;
        #pragma unroll
        for (int ks = 0; ks < 2; ++ks) {
            uint32_t ah[2][4], al[2][4];
            #pragma unroll
            for (int mi = 0; mi < 2; ++mi) {
                const uint32_t ro = (uint32_t)((wm0 + mi * 16 + lr + (g & 1) * 8) * 64
                                               + ks * 32 + (g >> 1) * 16);
                ldsm4u(ah[mi], st + SWZ64(ro));
                ldsm4u(al[mi], st + 8192 + SWZ64(ro));
            }
            #pragma unroll
            for (int np = 0; np < 4; ++np) {
                const uint32_t ro = (uint32_t)((wn0 + np * 16 + lr + (g >> 1) * 8) * 64
                                               + ks * 32 + (g & 1) * 16);
                uint32_t bh[4], bl[4];
                ldsm4u(bh, st + 16384 + SWZ64(ro));
                ldsm4u(bl, st + 24576 + SWZ64(ro));
                #pragma unroll
                for (int half = 0; half < 2; ++half) {
                    const int ni = np * 2 + half;
                    #pragma unroll
                    for (int mi = 0; mi < 2; ++mi) {
                        mma16816(acc[mi][ni], ah[mi], bh[half * 2], bh[half * 2 + 1]);
                        mma16816(acc[mi][ni], ah[mi], bl[half * 2], bl[half * 2 + 1]);
                        mma16816(acc[mi][ni], al[mi], bh[half * 2], bh[half * 2 + 1]);
                    }
                }
            }
        }
    }

    #pragma unroll
    for (int ni = 0; ni < 8; ++ni) {
        const int col = bn + wn0 + ni * 8 + (lane & 3) * 2;
        const float2 bv = *(const float2*)&bias[col];
        #pragma unroll
        for (int mi = 0; mi < 2; ++mi) {
            const int row = bm + wm0 + mi * 16 + (lane >> 2);
            *(float2*)&C[(size_t)row * N + col] =
                make_float2(acc[mi][ni][0] + bv.x, acc[mi][ni][1] + bv.y);
            *(float2*)&C[(size_t)(row + 8) * N + col] =
                make_float2(acc[mi][ni][2] + bv.x, acc[mi][ni][3] + bv.y);
        }
    }
}

// ---------------------------------------------------------------------------
// Causal flash attention, HMMA bf16x3, x4-ldmatrix loads.
// Round-9 champion config restored: __launch_bounds__(256, 1).
// ---------------------------------------------------------------------------
constexpr int ATTN_SMEM = 2 * 45056;   // 90112

__global__ __launch_bounds__(256, 1)
void attn_tc(const __nv_bfloat16* __restrict__ qh_g, const __nv_bfloat16* __restrict__ ql_g,
             const __nv_bfloat16* __restrict__ kh_g, const __nv_bfloat16* __restrict__ kl_g,
             const __nv_bfloat16* __restrict__ vh_g, const __nv_bfloat16* __restrict__ vl_g,
             __nv_bfloat16* __restrict__ chi, __nv_bfloat16* __restrict__ clo)
{
    extern __shared__ __align__(1024) char smc[];
    const uint32_t sb = smem_u32(smc);
    const int qt   = gridDim.x - 1 - blockIdx.x;   // big tiles first
    const int h    = blockIdx.y;
    const int b    = blockIdx.z;
    const int tid  = threadIdx.x;
    const int lane = tid & 31;
    const int wid  = tid >> 5;
    const int wm   = wid * 16;
    const int lr   = lane & 7;
    const int g    = lane >> 3;

    const size_t hb = ((size_t)(b * H_ + h)) * S_ * HD_;

    // ---- stage Q (hi at 0, lo at 22528) and load fragments ----
    for (int t = tid; t < 2560; t += 256) {
        const int arr = t / 1280, rem = t % 1280;
        const int row = rem / 10, c = rem % 10;
        const __nv_bfloat16* src = (arr ? ql_g : qh_g) + hb
                                   + (size_t)(qt * 128 + row) * HD_ + c * 8;
        cp_async16(sb + (uint32_t)(arr * 22528 + row * 176 + c * 16), src);
    }
    CP_COMMIT();
    asm volatile("cp.async.wait_group 0;" ::: "memory");
    __syncthreads();

    uint32_t qh[5][4], ql[5][4];
    #pragma unroll
    for (int ks = 0; ks < 5; ++ks) {
        const uint32_t ro = (uint32_t)((wm + lr + (g & 1) * 8) * 176 + ks * 32 + (g >> 1) * 16);
        ldsm4u(qh[ks], sb + ro);
        ldsm4u(ql[ks], sb + 22528 + ro);
    }
    __syncthreads();

    auto load_kv = [&](int kt) {
        const uint32_t st = sb + (uint32_t)(kt & 1) * 45056;
        const __nv_bfloat16* srcs[4] = { kh_g, kl_g, vh_g, vl_g };
        #pragma unroll
        for (int it = 0; it < 10; ++it) {
            const int t = tid + it * 256;
            const int arr = t / 640, rem = t % 640;
            const int row = rem / 10, c = rem % 10;
            const __nv_bfloat16* src = srcs[arr] + hb
                                       + (size_t)(kt * 64 + row) * HD_ + c * 8;
            cp_async16(st + (uint32_t)(arr * 11264 + row * 176 + c * 16), src);
        }
        CP_COMMIT();
    };

    float o[10][4] = {};
    float mx0 = -1e30f, mx1 = -1e30f, l0 = 0.f, l1 = 0.f;
    const int nkt = 2 * qt + 2;

    load_kv(0);

    // x4 ldmatrix lane-address components (conflict-free)
    const uint32_t krow = (uint32_t)(((lane >> 4) * 8 + lr) * 176 + ((lane >> 3) & 1) * 16);
    const uint32_t vrow = (uint32_t)((((lane >> 3) & 1) * 8 + lr) * 176 + (lane >> 4) * 16);

    for (int kt = 0; kt < nkt; ++kt) {
        if (kt + 1 < nkt) {
            load_kv(kt + 1);
            asm volatile("cp.async.wait_group 1;" ::: "memory");
        } else {
            asm volatile("cp.async.wait_group 0;" ::: "memory");
        }
        __syncthreads();

        const bool active = (qt * 128 + wm + 15 >= kt * 64);
        if (active) {
            const uint32_t st = sb + (uint32_t)(kt & 1) * 45056;

            // ---- scores S = Q K^T (bf16x3), 16 keys per ldsm.x4 ----
            float s[8][4];
            #pragma unroll
            for (int nb2 = 0; nb2 < 4; ++nb2) {
                float* sA = s[nb2 * 2];
                float* sB = s[nb2 * 2 + 1];
                sA[0] = sA[1] = sA[2] = sA[3] = 0.f;
                sB[0] = sB[1] = sB[2] = sB[3] = 0.f;
                const uint32_t rbase = st + (uint32_t)(nb2 * 16 * 176) + krow;
                #pragma unroll
                for (int ks = 0; ks < 5; ++ks) {
                    uint32_t kh4[4], kl4[4];
                    const uint32_t ro = rbase + ks * 32;
                    ldsm4u(kh4, ro);
                    ldsm4u(kl4, ro + 11264);
                    mma16816(sA, qh[ks], kh4[0], kh4[1]);
                    mma16816(sA, qh[ks], kl4[0], kl4[1]);
                    mma16816(sA, ql[ks], kh4[0], kh4[1]);
                    mma16816(sB, qh[ks], kh4[2], kh4[3]);
                    mma16816(sB, qh[ks], kl4[2], kl4[3]);
                    mma16816(sB, ql[ks], kh4[2], kh4[3]);
                }
            }
            if (kt >= 2 * qt) {   // diagonal-region mask
                const int r0 = qt * 128 + wm + (lane >> 2);
                #pragma unroll
                for (int nb = 0; nb < 8; ++nb) {
                    const int c0 = kt * 64 + nb * 8 + (lane & 3) * 2;
                    if (c0     > r0)     s[nb][0] = -1e30f;
                    if (c0 + 1 > r0)     s[nb][1] = -1e30f;
                    if (c0     > r0 + 8) s[nb][2] = -1e30f;
                    if (c0 + 1 > r0 + 8) s[nb][3] = -1e30f;
                }
            }

            // ---- online softmax ----
            float m0 = -1e30f, m1 = -1e30f;
            #pragma unroll
            for (int nb = 0; nb < 8; ++nb) {
                m0 = fmaxf(m0, fmaxf(s[nb][0], s[nb][1]));
                m1 = fmaxf(m1, fmaxf(s[nb][2], s[nb][3]));
            }
            m0 = fmaxf(m0, __shfl_xor_sync(0xffffffffu, m0, 1));
            m0 = fmaxf(m0, __shfl_xor_sync(0xffffffffu, m0, 2));
            m1 = fmaxf(m1, __shfl_xor_sync(0xffffffffu, m1, 1));
            m1 = fmaxf(m1, __shfl_xor_sync(0xffffffffu, m1, 2));
            const float mn0 = fmaxf(mx0, m0), mn1 = fmaxf(mx1, m1);
            const float corr0 = __expf(mx0 - mn0), corr1 = __expf(mx1 - mn1);
            mx0 = mn0; mx1 = mn1;
            float sum0 = 0.f, sum1 = 0.f;
            #pragma unroll
            for (int nb = 0; nb < 8; ++nb) {
                s[nb][0] = __expf(s[nb][0] - mn0);
                s[nb][1] = __expf(s[nb][1] - mn0);
                s[nb][2] = __expf(s[nb][2] - mn1);
                s[nb][3] = __expf(s[nb][3] - mn1);
                sum0 += s[nb][0] + s[nb][1];
                sum1 += s[nb][2] + s[nb][3];
            }
            sum0 += __shfl_xor_sync(0xffffffffu, sum0, 1);
            sum0 += __shfl_xor_sync(0xffffffffu, sum0, 2);
            sum1 += __shfl_xor_sync(0xffffffffu, sum1, 1);
            sum1 += __shfl_xor_sync(0xffffffffu, sum1, 2);
            l0 = l0 * corr0 + sum0;
            l1 = l1 * corr1 + sum1;
            #pragma unroll
            for (int nd = 0; nd < 10; ++nd) {
                o[nd][0] *= corr0; o[nd][1] *= corr0;
                o[nd][2] *= corr1; o[nd][3] *= corr1;
            }

            // ---- P -> bf16 hi/lo fragments ----
            uint32_t ph[4][4], pl[4][4];
            #pragma unroll
            for (int kb = 0; kb < 4; ++kb) {
                split2(s[2 * kb][0],     s[2 * kb][1],     ph[kb][0], pl[kb][0]);
                split2(s[2 * kb][2],     s[2 * kb][3],     ph[kb][1], pl[kb][1]);
                split2(s[2 * kb + 1][0], s[2 * kb + 1][1], ph[kb][2], pl[kb][2]);
                split2(s[2 * kb + 1][2], s[2 * kb + 1][3], ph[kb][3], pl[kb][3]);
            }

            // ---- O += P V (bf16x3), two nd blocks per ldsm.x4.trans ----
            #pragma unroll
            for (int nd2 = 0; nd2 < 5; ++nd2) {
                float* oA = o[nd2 * 2];
                float* oB = o[nd2 * 2 + 1];
                const uint32_t cbase = st + 22528 + (uint32_t)(nd2 * 32) + vrow;
                #pragma unroll
                for (int kb = 0; kb < 4; ++kb) {
                    uint32_t vh4[4], vl4[4];
                    const uint32_t ro = cbase + (uint32_t)(kb * 16 * 176);
                    ldsm4t(vh4, ro);
                    ldsm4t(vl4, ro + 11264);
                    mma16816(oA, ph[kb], vh4[0], vh4[1]);
                    mma16816(oA, ph[kb], vl4[0], vl4[1]);
                    mma16816(oA, pl[kb], vh4[0], vh4[1]);
                    mma16816(oB, ph[kb], vh4[2], vh4[3]);
                    mma16816(oB, ph[kb], vl4[2], vl4[3]);
                    mma16816(oB, pl[kb], vh4[2], vh4[3]);
                }
            }
        }
        __syncthreads();
    }

    const float inv0 = 1.f / l0, inv1 = 1.f / l1;
    const int r0 = qt * 128 + wm + (lane >> 2);
    #pragma unroll
    for (int nd = 0; nd < 10; ++nd) {
        const int col = h * HD_ + nd * 8 + (lane & 3) * 2;
        uint32_t hi, lo;
        split2(o[nd][0] * inv0, o[nd][1] * inv0, hi, lo);
        *(uint32_t*)&chi[((size_t)(b * S_ + r0)) * D_ + col] = hi;
        *(uint32_t*)&clo[((size_t)(b * S_ + r0)) * D_ + col] = lo;
        split2(o[nd][2] * inv1, o[nd][3] * inv1, hi, lo);
        *(uint32_t*)&chi[((size_t)(b * S_ + r0 + 8)) * D_ + col] = hi;
        *(uint32_t*)&clo[((size_t)(b * S_ + r0 + 8)) * D_ + col] = lo;
    }
}

// ---------------------------------------------------------------------------
// Launch
// ---------------------------------------------------------------------------
extern "C" void kernel_launch(void* const* d_in, const int* in_sizes, int n_in,
                              void* d_out, int out_size)
{
    const float* x      = (const float*)d_in[0];
    const float* wqkv_w = (const float*)d_in[1];
    const float* wqkv_b = (const float*)d_in[2];
    const float* out_w  = (const float*)d_in[3];
    const float* out_b  = (const float*)d_in[4];
    float* out = (float*)d_out;

    float* qkv;
    __nv_bfloat16 *ahi, *alo, *whi, *wlo, *ohi, *olo;
    __nv_bfloat16 *qh, *ql, *kh, *kl, *vh, *vl;
    cudaGetSymbolAddress((void**)&qkv, g_qkv);
    cudaGetSymbolAddress((void**)&ahi, g_ahi);
    cudaGetSymbolAddress((void**)&alo, g_alo);
    cudaGetSymbolAddress((void**)&whi, g_whi);
    cudaGetSymbolAddress((void**)&wlo, g_wlo);
    cudaGetSymbolAddress((void**)&ohi, g_ohi);
    cudaGetSymbolAddress((void**)&olo, g_olo);
    cudaGetSymbolAddress((void**)&qh, g_qh);
    cudaGetSymbolAddress((void**)&ql, g_ql);
    cudaGetSymbolAddress((void**)&kh, g_kh);
    cudaGetSymbolAddress((void**)&kl, g_kl);
    cudaGetSymbolAddress((void**)&vh, g_vh);
    cudaGetSymbolAddress((void**)&vl, g_vl);

    cudaFuncSetAttribute(gemm_hmma,
                         cudaFuncAttributeMaxDynamicSharedMemorySize, GEMM_SMEM);
    cudaFuncSetAttribute(attn_tc,
                         cudaFuncAttributeMaxDynamicSharedMemorySize, ATTN_SMEM);

    // 0) rope table + split x / weights into bf16 hi/lo
    rope_table_kernel<<<S_ * 16 / 256, 256>>>();
    {
        const int n4x = M_ROWS * D_ / 4;
        cvt_split<<<n4x / 256, 256>>>((const float4*)x, (uint2*)ahi, (uint2*)alo, n4x);
        const int n4w = QKV_N * D_ / 4;
        cvt_split<<<n4w / 256, 256>>>((const float4*)wqkv_w, (uint2*)whi, (uint2*)wlo, n4w);
        const int n4o = D_ * D_ / 4;
        cvt_split<<<n4o / 256, 256>>>((const float4*)out_w, (uint2*)ohi, (uint2*)olo, n4o);
    }

    // 1) QKV = X @ Wqkv^T + b
    dim3 g1(QKV_N / 128, M_ROWS / 128);
    gemm_hmma<<<g1, 256, GEMM_SMEM>>>(ahi, alo, whi, wlo, wqkv_b, qkv,
                                      M_ROWS, QKV_N, D_);

    // 2) fused RoPE(table) + scale + split qkv -> head-major bf16 hi/lo
    cvt_qkv<<<(M_ROWS * QKV_N / 4) / 256, 256>>>((const float4*)qkv);

    // 3) causal attention -> ctx (written directly as hi/lo into ahi/alo)
    dim3 ga(S_ / 128, H_, B_);
    attn_tc<<<ga, 256, ATTN_SMEM>>>(qh, ql, kh, kl, vh, vl, ahi, alo);

    // 4) out = ctx @ Wout^T + b
    dim3 g2(D_ / 128, M_ROWS / 128);
    gemm_hmma<<<g2, 256, GEMM_SMEM>>>(ahi, alo, ohi, olo, out_b, out,
                                      M_ROWS, D_, D_);
}